// round 16
// baseline (speedup 1.0000x reference)
#include <cuda_runtime.h>
#include <math.h>
#include <stdint.h>

#define B_TOK 2048
#define E_EXP 16
#define TOPK  4
#define D_IN  1536
#define H_DIM 1024
#define NHEAD 204
#define NHEAD_PAD 256
#define CAP   2048
#define EPS_F 2.220446049250313e-16f

// shared tiling params
#define BM 128
#define BK 32
#define KPW 16
#define A_STRIDE 20
#define A_STAGE (BM * A_STRIDE * 4)
#define NSTAGE 6

// main GEMM: BN=256, 512 threads, k-major B (transposed weights)
#define BNW 256
#define BT_STRIDE 20
#define BT_STAGE (BNW * BT_STRIDE * 4)     // 20480
#define STAGE_W (A_STAGE + BT_STAGE)       // 30720
#define SMEM_MAIN (NSTAGE * STAGE_W)       // 184320

// heads GEMM: BN=128, 256 threads, n-contig B (proven, unchanged)
#define BNH 128
#define BH_STRIDE 136
#define BH_STAGE (16 * BH_STRIDE * 4)
#define STAGE_H (A_STAGE + BH_STAGE)
#define SMEM_HEADS (NSTAGE * STAGE_H)      // 113664

// prep kernel block ranges
#define G_BLKS  2048
#define W1_BLKS 12288     // 16e * 24 kp-tiles * 32 n-tiles
#define W2_BLKS 8192      // 16e * 16 kp-tiles * 32 n-tiles
#define PH_BLKS 8192
#define PREP_BLKS (G_BLKS + W1_BLKS + W2_BLKS + PH_BLKS)

// ---------------- scratch ----------------
__device__ __align__(16) uint32_t g_xb[(size_t)B_TOK * (D_IN / 2)];
__device__ int   g_rows[E_EXP * CAP];
__device__ int   g_cnt[E_EXP];
__device__ float g_gate[B_TOK * TOPK];
__device__ int   g_slot[B_TOK * TOPK];
__device__ __align__(16) uint32_t g_h1[(size_t)E_EXP * CAP * (H_DIM / 2)];
__device__ __align__(16) uint32_t g_h2[(size_t)E_EXP * CAP * (H_DIM / 2)];
__device__ __align__(16) float    g_hl[(size_t)E_EXP * CAP * NHEAD_PAD];
__device__ __align__(16) float    g_hl2[(size_t)E_EXP * CAP * NHEAD_PAD];
__device__ __align__(16) uint32_t g_w1t[(size_t)E_EXP * H_DIM * (D_IN / 2)];   // [e][n=1024][kp=768]
__device__ __align__(16) uint32_t g_w2t[(size_t)E_EXP * H_DIM * (H_DIM / 2)];  // [e][n=1024][kp=512]
__device__ __align__(16) uint32_t g_whb[(size_t)E_EXP * (H_DIM / 2) * NHEAD_PAD]; // [e][kp=512][n=256]
__device__ float g_bh[E_EXP * NHEAD_PAD];

// ---------------- helpers ----------------
__device__ __forceinline__ uint32_t smem_u32(const void* p) {
    uint32_t a;
    asm("{ .reg .u64 t; cvta.to.shared.u64 t, %1; cvt.u32.u64 %0, t; }" : "=r"(a) : "l"(p));
    return a;
}
__device__ __forceinline__ uint32_t packbf(float lo, float hi) {
    uint32_t w;
    asm("cvt.rn.bf16x2.f32 %0, %1, %2;" : "=r"(w) : "f"(hi), "f"(lo));
    return w;
}
__device__ __forceinline__ void cp16(uint32_t dst, const void* src) {
    asm volatile("cp.async.cg.shared.global [%0], [%1], 16;" :: "r"(dst), "l"(src));
}
__device__ __forceinline__ void mma_bf16(float* c, const uint32_t* a, const uint32_t* b) {
    asm volatile("mma.sync.aligned.m16n8k16.row.col.f32.bf16.bf16.f32 "
        "{%0,%1,%2,%3}, {%4,%5,%6,%7}, {%8,%9}, {%0,%1,%2,%3};"
        : "+f"(c[0]), "+f"(c[1]), "+f"(c[2]), "+f"(c[3])
        : "r"(a[0]), "r"(a[1]), "r"(a[2]), "r"(a[3]), "r"(b[0]), "r"(b[1]));
}
__device__ __forceinline__ void ldm_x4(uint32_t* r, uint32_t addr) {
    asm volatile("ldmatrix.sync.aligned.m8n8.x4.shared.b16 {%0,%1,%2,%3}, [%4];"
        : "=r"(r[0]), "=r"(r[1]), "=r"(r[2]), "=r"(r[3]) : "r"(addr));
}

// ---------------- transposed conv: f32 [E][K][N=1024] -> bf16x2 [E][N][K/2] ----------------
__device__ __forceinline__ void conv_t_body(const float* __restrict__ src,
                                            uint32_t* __restrict__ dst,
                                            int Kw, int bb, float* sm /*64*33*/) {
    const int t = threadIdx.x;
    const int kpTiles = Kw >> 5;
    const int per_e = kpTiles << 5;
    const int e  = bb / per_e;
    const int rem = bb % per_e;
    const int kp0 = (rem >> 5) << 5;
    const int n0  = (rem & 31) << 5;
    const int K = Kw * 2;

    #pragma unroll
    for (int it = 0; it < 2; it++) {
        int f = t + it * 256;
        int row = f >> 3, col4 = (f & 7) * 4;
        const float4 v = *(const float4*)(src + ((size_t)e * K + 2 * kp0 + row) * 1024 + n0 + col4);
        sm[row * 33 + col4 + 0] = v.x;
        sm[row * 33 + col4 + 1] = v.y;
        sm[row * 33 + col4 + 2] = v.z;
        sm[row * 33 + col4 + 3] = v.w;
    }
    __syncthreads();

    int nl = t >> 3, kg = (t & 7) * 4;
    uint4 o;
    o.x = packbf(sm[(2 * (kg + 0)) * 33 + nl], sm[(2 * (kg + 0) + 1) * 33 + nl]);
    o.y = packbf(sm[(2 * (kg + 1)) * 33 + nl], sm[(2 * (kg + 1) + 1) * 33 + nl]);
    o.z = packbf(sm[(2 * (kg + 2)) * 33 + nl], sm[(2 * (kg + 2) + 1) * 33 + nl]);
    o.w = packbf(sm[(2 * (kg + 3)) * 33 + nl], sm[(2 * (kg + 3) + 1) * 33 + nl]);
    *(uint4*)(dst + ((size_t)e * 1024 + n0 + nl) * Kw + kp0 + kg) = o;
    __syncthreads();
}

// ---------------- fused prep: gating + W1 conv-t + W2 conv-t + head pack ----------------
__global__ void __launch_bounds__(256)
prep_kernel(const float* __restrict__ sf, const float* __restrict__ of,
            const float* __restrict__ ppf, const float* __restrict__ pvf,
            const float* __restrict__ wg, const float* __restrict__ wn,
            const float* __restrict__ noise,
            const float* __restrict__ W1, const float* __restrict__ W2,
            const float* __restrict__ Ws, const float* __restrict__ bs,
            const float* __restrict__ Wo, const float* __restrict__ bo,
            const float* __restrict__ Wp, const float* __restrict__ bp) {
    int bb = blockIdx.x;
    int t = threadIdx.x;
    __shared__ float smt[64 * 33];

    if (bb >= G_BLKS) {
        bb -= G_BLKS;
        if (bb < W1_BLKS) { conv_t_body(W1, g_w1t, D_IN / 2, bb, smt); return; }
        bb -= W1_BLKS;
        if (bb < W2_BLKS) { conv_t_body(W2, g_w2t, H_DIM / 2, bb, smt); return; }
        bb -= W2_BLKS;
        size_t idx = (size_t)bb * 256 + t;
        int n  = (int)(idx & 255);
        int kp = (int)((idx >> 8) & 511);
        int e  = (int)(idx >> 17);
        float lo = 0.f, hi = 0.f;
        size_t base0 = (size_t)e * H_DIM + 2 * kp;
        if (n < 36)       { lo = Ws[base0 * 36 + n];         hi = Ws[(base0 + 1) * 36 + n]; }
        else if (n < 72)  { lo = Wo[base0 * 36 + (n - 36)];  hi = Wo[(base0 + 1) * 36 + (n - 36)]; }
        else if (n < 204) { lo = Wp[base0 * 132 + (n - 72)]; hi = Wp[(base0 + 1) * 132 + (n - 72)]; }
        g_whb[idx] = packbf(lo, hi);
        if (idx < E_EXP * NHEAD_PAD) {
            int nn = (int)(idx & 255), ee = (int)(idx >> 8);
            float b = 0.0f;
            if (nn < 36)       b = bs[ee * 36 + nn];
            else if (nn < 72)  b = bo[ee * 36 + (nn - 36)];
            else if (nn < 204) b = bp[ee * 132 + (nn - 72)];
            g_bh[idx] = b;
        }
        return;
    }

    // ----- gating block -----
    int b = bb;
    __shared__ __align__(16) float sx[D_IN];
    __shared__ float part[8][32];

    for (int i = t; i < D_IN; i += 256) {
        float v;
        if (i < 512)        v = sf[b * 512 + i];
        else if (i < 1024)  v = of[b * 512 + (i - 512)];
        else if (i < 1280)  v = ppf[b * 256 + (i - 1024)];
        else                v = pvf[b * 256 + (i - 1280)];
        sx[i] = v;
    }
    __syncthreads();

    int w = t >> 5, lane = t & 31;
    int e = lane & 15;
    const float* wm = (lane < 16) ? wg : wn;
    int d0 = w * 192;
    float a0 = 0.f, a1 = 0.f, a2 = 0.f, a3 = 0.f;
    #pragma unroll 4
    for (int d = d0; d < d0 + 192; d += 4) {
        a0 += sx[d + 0] * wm[(d + 0) * 16 + e];
        a1 += sx[d + 1] * wm[(d + 1) * 16 + e];
        a2 += sx[d + 2] * wm[(d + 2) * 16 + e];
        a3 += sx[d + 3] * wm[(d + 3) * 16 + e];
    }
    part[w][lane] = (a0 + a1) + (a2 + a3);
    __syncthreads();

    if (t < 32) {
        float s = 0.f;
        #pragma unroll
        for (int w2 = 0; w2 < 8; w2++) s += part[w2][t];
        part[0][t] = s;
    }
    __syncthreads();

    if (t == 0) {
        float logits[16];
        #pragma unroll
        for (int i = 0; i < 16; i++) {
            float cl = part[0][i];
            float z  = part[0][16 + i];
            float sp = (z > 20.f) ? z : log1pf(expf(z));
            logits[i] = cl + noise[b * 16 + i] * (sp + 1e-2f);
        }
        int   idx[TOPK];
        float val[TOPK];
        unsigned used = 0u;
        for (int k = 0; k < TOPK; k++) {
            float best = -INFINITY; int bi = 0;
            for (int i = 0; i < 16; i++)
                if (!((used >> i) & 1u) && logits[i] > best) { best = logits[i]; bi = i; }
            used |= (1u << bi); idx[k] = bi; val[k] = best;
        }
        float m = val[0];
        float g[TOPK], s = 0.f;
        #pragma unroll
        for (int k = 0; k < TOPK; k++) { g[k] = expf(val[k] - m); s += g[k]; }
        #pragma unroll
        for (int k = 0; k < TOPK; k++) {
            int ex = idx[k];
            int rank = atomicAdd(&g_cnt[ex], 1);
            int slot = ex * CAP + rank;
            g_rows[slot]       = b;
            g_slot[b * 4 + k]  = slot;
            g_gate[b * 4 + k]  = g[k] / s;
        }
    }

    uint32_t* dst = g_xb + (size_t)b * (D_IN / 2);
    for (int i = t; i < D_IN / 2; i += 256)
        dst[i] = packbf(sx[2 * i], sx[2 * i + 1]);
}

// ---------------- main bf16 GEMM: 128x256 tile, 512 threads, k-major B, ldmatrix both ops ----------------
template<bool GATHER>
__global__ void __launch_bounds__(512, 1)
gemm_main(const uint32_t* __restrict__ A, const uint32_t* __restrict__ Bt,
          const float* __restrict__ bias, uint32_t* __restrict__ C,
          int Ktot, int Ntot) {
    extern __shared__ char smem[];
    const int e  = blockIdx.z;
    const int M  = g_cnt[e];
    const int m0 = blockIdx.y * BM;
    if (m0 >= M) return;
    const int n0 = blockIdx.x * BNW;

    const uint32_t sbase = smem_u32(smem);
    const int tid = threadIdx.x;
    const int wid = tid >> 5, lane = tid & 31;
    const int wm = wid >> 3;
    const int wn = wid & 7;
    const int r  = lane >> 2;
    const int c  = lane & 3;

    const int Kw = Ktot / 2;
    const int KT = Ktot / BK;

    const int a_row = tid >> 2;
    const int a_ch  = tid & 3;
    const int b_row = tid >> 1;
    const int b_ch  = (tid & 1) * 2;

    const uint32_t* ga_row;
    if (GATHER) {
        int mg = m0 + a_row;
        if (mg >= M) mg = M - 1;
        ga_row = A + (size_t)g_rows[e * CAP + mg] * Kw;
    } else {
        ga_row = A + (size_t)(e * CAP + m0 + a_row) * Kw;
    }
    const uint32_t* gb_row = Bt + ((size_t)e * Ntot + n0 + b_row) * Kw;

    auto load_stage = [&](int kt) {
        int slot = kt % NSTAGE;
        uint32_t sa = sbase + slot * STAGE_W;
        uint32_t sb = sa + A_STAGE;
        cp16(sa + a_row * (A_STRIDE * 4) + a_ch * 16, ga_row + kt * KPW + a_ch * 4);
        cp16(sb + b_row * (BT_STRIDE * 4) + b_ch * 16,       gb_row + kt * KPW + b_ch * 4);
        cp16(sb + b_row * (BT_STRIDE * 4) + (b_ch + 1) * 16, gb_row + kt * KPW + (b_ch + 1) * 4);
        asm volatile("cp.async.commit_group;" ::: "memory");
    };

    load_stage(0);
    load_stage(1);
    load_stage(2);
    load_stage(3);

    float acc[4][4][4];
    #pragma unroll
    for (int i = 0; i < 4; i++)
        #pragma unroll
        for (int j = 0; j < 4; j++)
            #pragma unroll
            for (int k = 0; k < 4; k++) acc[i][j][k] = 0.f;

    const int lrow = lane & 7;
    // A fragments (R7-proven): bit3 -> row-pair select, bit4 -> k-chunk select
    const int a_rsel = (lane >> 3) & 1;
    const int a_ksel = (lane >> 4) & 1;
    const uint32_t a_lm = sbase
        + ((wm * 64 + a_rsel * 8 + lrow) * A_STRIDE) * 4
        + a_ksel * 16;
    // B fragments: bit3 -> k-chunk select, bit4 -> n-row select
    const int b_ksel = (lane >> 3) & 1;
    const int b_rsel = (lane >> 4) & 1;
    const uint32_t b_lm = sbase + A_STAGE
        + ((wn * 32 + b_rsel * 8 + lrow) * BT_STRIDE) * 4
        + b_ksel * 16;

    auto process = [&](int s) {
        int slot = s % NSTAGE;
        uint32_t sa = a_lm + slot * STAGE_W;
        uint32_t sb = b_lm + slot * STAGE_W;
        #pragma unroll
        for (int ks = 0; ks < 2; ks++) {
            uint32_t af[4][4];
            #pragma unroll
            for (int mt = 0; mt < 4; mt++)
                ldm_x4(af[mt], sa + mt * (16 * A_STRIDE * 4) + ks * 32);
            uint32_t bf[4][2];
            #pragma unroll
            for (int p = 0; p < 2; p++) {
                uint32_t q[4];
                ldm_x4(q, sb + p * (16 * BT_STRIDE * 4) + ks * 32);
                bf[2 * p][0]     = q[0];
                bf[2 * p][1]     = q[1];
                bf[2 * p + 1][0] = q[2];
                bf[2 * p + 1][1] = q[3];
            }
            #pragma unroll
            for (int mt = 0; mt < 4; mt++)
                #pragma unroll
                for (int nt = 0; nt < 4; nt++)
                    mma_bf16(acc[mt][nt], af[mt], bf[nt]);
        }
    };

    for (int kt = 0; kt < KT; kt += 2) {
        asm volatile("cp.async.wait_group 2;" ::: "memory");
        __syncthreads();
        if (kt + 4 < KT) load_stage(kt + 4);
        else asm volatile("cp.async.commit_group;" ::: "memory");
        if (kt + 5 < KT) load_stage(kt + 5);
        else asm volatile("cp.async.commit_group;" ::: "memory");
        process(kt);
        process(kt + 1);
    }
    asm volatile("cp.async.wait_group 0;" ::: "memory");

    #pragma unroll
    for (int nt = 0; nt < 4; nt++) {
        int col = n0 + wn * 32 + nt * 8 + 2 * c;
        float bb0 = __ldg(bias + e * Ntot + col);
        float bb1 = __ldg(bias + e * Ntot + col + 1);
        #pragma unroll
        for (int mt = 0; mt < 4; mt++) {
            int row0 = wm * 64 + mt * 16 + r;
            float v0 = fmaxf(acc[mt][nt][0] + bb0, 0.f);
            float v1 = fmaxf(acc[mt][nt][1] + bb1, 0.f);
            float v2 = fmaxf(acc[mt][nt][2] + bb0, 0.f);
            float v3 = fmaxf(acc[mt][nt][3] + bb1, 0.f);
            int cw = col >> 1;
            if (m0 + row0 < M)
                C[(size_t)(e * CAP + m0 + row0) * (Ntot / 2) + cw] = packbf(v0, v1);
            if (m0 + row0 + 8 < M)
                C[(size_t)(e * CAP + m0 + row0 + 8) * (Ntot / 2) + cw] = packbf(v2, v3);
        }
    }
}

// ---------------- heads GEMM, split-K=2, BN=128 (unchanged) ----------------
__global__ void __launch_bounds__(256, 2)
gemm_heads(const uint32_t* __restrict__ A, const uint32_t* __restrict__ B) {
    extern __shared__ char smem[];
    const int zz = blockIdx.z;
    const int e  = zz & 15;
    const int sp = zz >> 4;
    const int M  = g_cnt[e];
    const int m0 = blockIdx.y * BM;
    if (m0 >= M) return;
    const int n0 = blockIdx.x * BNH;

    const uint32_t sbase = smem_u32(smem);
    const int tid = threadIdx.x;
    const int wid = tid >> 5, lane = tid & 31;
    const int wm = wid >> 2;
    const int wn = wid & 3;
    const int r  = lane >> 2;
    const int c  = lane & 3;

    const int Kw = H_DIM / 2;
    const int KT = (H_DIM / 2) / BK;
    const uint32_t* Abase = A + (size_t)(e * CAP + m0) * Kw + sp * (Kw / 2);
    const uint32_t* Bbase = B + ((size_t)e * Kw + sp * (Kw / 2)) * NHEAD_PAD + n0;
    float* C = (sp ? g_hl2 : g_hl);

    const int a_row = tid >> 1;
    const int a_ch  = (tid & 1) * 2;
    const int b_row = tid >> 4;
    const int b_ch  = (tid & 15) * 2;

    auto load_stage = [&](int kt) {
        int slot = kt % NSTAGE;
        uint32_t sa = sbase + slot * STAGE_H;
        uint32_t sb = sa + A_STAGE;
        const uint32_t* ga = Abase + kt * KPW;
        const uint32_t* gb = Bbase + (size_t)(kt * 16) * NHEAD_PAD;
        cp16(sa + a_row * (A_STRIDE * 4) + a_ch * 16,       ga + (size_t)a_row * Kw + a_ch * 4);
        cp16(sa + a_row * (A_STRIDE * 4) + (a_ch + 1) * 16, ga + (size_t)a_row * Kw + (a_ch + 1) * 4);
        cp16(sb + b_row * (BH_STRIDE * 4) + b_ch * 16,       gb + (size_t)b_row * NHEAD_PAD + b_ch * 4);
        cp16(sb + b_row * (BH_STRIDE * 4) + (b_ch + 1) * 16, gb + (size_t)b_row * NHEAD_PAD + (b_ch + 1) * 4);
        asm volatile("cp.async.commit_group;" ::: "memory");
    };

    load_stage(0);
    load_stage(1);
    load_stage(2);
    load_stage(3);

    float acc[4][4][4];
    #pragma unroll
    for (int i = 0; i < 4; i++)
        #pragma unroll
        for (int j = 0; j < 4; j++)
            #pragma unroll
            for (int k = 0; k < 4; k++) acc[i][j][k] = 0.f;

    const int lrow = lane & 7;
    const int lsel = lane >> 3;
    const uint32_t a_lm = sbase
        + ((wm * 64 + (lsel & 1) * 8 + lrow) * A_STRIDE) * 4
        + (lsel >> 1) * 16;
    const uint32_t b_fb = sbase + A_STAGE + (c * BH_STRIDE + wn * 32 + r) * 4;

    auto process = [&](int s) {
        int slot = s % NSTAGE;
        uint32_t sa = a_lm + slot * STAGE_H;
        uint32_t sb = b_fb + slot * STAGE_H;
        #pragma unroll
        for (int ks = 0; ks < 2; ks++) {
            uint32_t af[4][4];
            #pragma unroll
            for (int mt = 0; mt < 4; mt++)
                ldm_x4(af[mt], sa + mt * (16 * A_STRIDE * 4) + ks * 32);
            uint32_t bf[4][2];
            #pragma unroll
            for (int nt = 0; nt < 4; nt++) {
                uint32_t base = sb + ks * (8 * BH_STRIDE * 4) + nt * 32;
                asm volatile("ld.shared.b32 %0, [%1];" : "=r"(bf[nt][0]) : "r"(base));
                asm volatile("ld.shared.b32 %0, [%1];" : "=r"(bf[nt][1]) : "r"(base + 4 * BH_STRIDE * 4));
            }
            #pragma unroll
            for (int mt = 0; mt < 4; mt++)
                #pragma unroll
                for (int nt = 0; nt < 4; nt++)
                    mma_bf16(acc[mt][nt], af[mt], bf[nt]);
        }
    };

    for (int kt = 0; kt < KT; kt += 2) {
        asm volatile("cp.async.wait_group 2;" ::: "memory");
        __syncthreads();
        if (kt + 4 < KT) load_stage(kt + 4);
        else asm volatile("cp.async.commit_group;" ::: "memory");
        if (kt + 5 < KT) load_stage(kt + 5);
        else asm volatile("cp.async.commit_group;" ::: "memory");
        process(kt);
        process(kt + 1);
    }
    asm volatile("cp.async.wait_group 0;" ::: "memory");

    #pragma unroll
    for (int nt = 0; nt < 4; nt++) {
        int col = n0 + wn * 32 + nt * 8 + 2 * c;
        #pragma unroll
        for (int mt = 0; mt < 4; mt++) {
            int row0 = wm * 64 + mt * 16 + r;
            if (m0 + row0 < M) {
                float2 p = {acc[mt][nt][0], acc[mt][nt][1]};
                *(float2*)(C + (size_t)(e * CAP + m0 + row0) * NHEAD_PAD + col) = p;
            }
            if (m0 + row0 + 8 < M) {
                float2 p = {acc[mt][nt][2], acc[mt][nt][3]};
                *(float2*)(C + (size_t)(e * CAP + m0 + row0 + 8) * NHEAD_PAD + col) = p;
            }
        }
    }
}

// ---------------- combine ----------------
__global__ void combine_kernel(float* __restrict__ out) {
    int b = blockIdx.x;
    __shared__ float vals[TOPK][NHEAD];
    __shared__ float mx[TOPK][3], inv[TOPK][3];
    __shared__ int   slots[TOPK];
    __shared__ float gts[TOPK];
    int t = threadIdx.x;

    if (b == 0 && t >= 32 && t < 32 + E_EXP) g_cnt[t - 32] = 0;

    if (t < TOPK) { slots[t] = g_slot[b * 4 + t]; gts[t] = g_gate[b * 4 + t]; }
    __syncthreads();

    for (int i = t; i < TOPK * NHEAD; i += 256) {
        int k = i / NHEAD, cc = i % NHEAD;
        int slot = slots[k];
        int e = slot >> 11;
        vals[k][cc] = g_hl[(size_t)slot * NHEAD_PAD + cc]
                    + g_hl2[(size_t)slot * NHEAD_PAD + cc]
                    + g_bh[e * NHEAD_PAD + cc];
    }
    __syncthreads();

    if (t < TOPK * 3) {
        int k = t / 3, grp = t % 3;
        int c0 = (grp == 0) ? 0 : (grp == 1 ? 36 : 72);
        int c1 = (grp == 0) ? 36 : (grp == 1 ? 72 : 204);
        float m = -INFINITY;
        for (int cc = c0; cc < c1; cc++) m = fmaxf(m, vals[k][cc]);
        float s = 0.f;
        for (int cc = c0; cc < c1; cc++) s += expf(vals[k][cc] - m);
        mx[k][grp]  = m;
        inv[k][grp] = 1.f / s;
    }
    __syncthreads();

    if (t < NHEAD) {
        int grp = (t < 36) ? 0 : ((t < 72) ? 1 : 2);
        float s = 0.f;
        #pragma unroll
        for (int k = 0; k < TOPK; k++)
            s += gts[k] * expf(vals[k][t] - mx[k][grp]) * inv[k][grp];
        float res = logf((s == 0.f) ? EPS_F : s);
        if (t < 36)       out[b * 36 + t] = res;
        else if (t < 72)  out[B_TOK * 36 + b * 36 + (t - 36)] = res;
        else              out[B_TOK * 72 + b * 132 + (t - 72)] = res;
    }
}

// ---------------- launch ----------------
extern "C" void kernel_launch(void* const* d_in, const int* in_sizes, int n_in,
                              void* d_out, int out_size) {
    const float* sf  = (const float*)d_in[0];
    const float* of  = (const float*)d_in[1];
    const float* ppf = (const float*)d_in[2];
    const float* pvf = (const float*)d_in[3];
    const float* wg  = (const float*)d_in[4];
    const float* wn  = (const float*)d_in[5];
    const float* W1  = (const float*)d_in[6];
    const float* b1  = (const float*)d_in[7];
    const float* W2  = (const float*)d_in[8];
    const float* b2  = (const float*)d_in[9];
    const float* Ws  = (const float*)d_in[10];
    const float* bs  = (const float*)d_in[11];
    const float* Wo  = (const float*)d_in[12];
    const float* bo  = (const float*)d_in[13];
    const float* Wp  = (const float*)d_in[14];
    const float* bp  = (const float*)d_in[15];
    const float* noise = (const float*)d_in[16];
    float* out = (float*)d_out;

    static uint32_t* p_xb  = nullptr;
    static uint32_t* p_h1  = nullptr;
    static uint32_t* p_h2  = nullptr;
    static uint32_t* p_w1t = nullptr;
    static uint32_t* p_w2t = nullptr;
    static uint32_t* p_whb = nullptr;
    if (!p_xb) {
        cudaGetSymbolAddress((void**)&p_xb,  g_xb);
        cudaGetSymbolAddress((void**)&p_h1,  g_h1);
        cudaGetSymbolAddress((void**)&p_h2,  g_h2);
        cudaGetSymbolAddress((void**)&p_w1t, g_w1t);
        cudaGetSymbolAddress((void**)&p_w2t, g_w2t);
        cudaGetSymbolAddress((void**)&p_whb, g_whb);
        cudaFuncSetAttribute(gemm_main<true>,
                             cudaFuncAttributeMaxDynamicSharedMemorySize, SMEM_MAIN);
        cudaFuncSetAttribute(gemm_main<false>,
                             cudaFuncAttributeMaxDynamicSharedMemorySize, SMEM_MAIN);
        cudaFuncSetAttribute(gemm_heads,
                             cudaFuncAttributeMaxDynamicSharedMemorySize, SMEM_HEADS);
    }

    prep_kernel<<<PREP_BLKS, 256>>>(sf, of, ppf, pvf, wg, wn, noise,
                                    W1, W2, Ws, bs, Wo, bo, Wp, bp);

    // L1: gathered rows of x @ W1t[e] (k-major) -> relu -> h1
    gemm_main<true><<<dim3(H_DIM / BNW, CAP / BM, E_EXP), 512, SMEM_MAIN>>>(
        p_xb, p_w1t, b1, p_h1, D_IN, H_DIM);
    // L2: h1 @ W2t[e] (k-major) -> relu -> h2
    gemm_main<false><<<dim3(H_DIM / BNW, CAP / BM, E_EXP), 512, SMEM_MAIN>>>(
        p_h1, p_w2t, b2, p_h2, H_DIM, H_DIM);
    // heads: split-K=2, n-contig B (unchanged)
    gemm_heads<<<dim3(NHEAD_PAD / BNH, CAP / BM, 2 * E_EXP), 256, SMEM_HEADS>>>(p_h2, p_whb);

    combine_kernel<<<B_TOK, 256>>>(out);
}

// round 17
// speedup vs baseline: 1.0344x; 1.0344x over previous
#include <cuda_runtime.h>
#include <math.h>
#include <stdint.h>

#define B_TOK 2048
#define E_EXP 16
#define TOPK  4
#define D_IN  1536
#define H_DIM 1024
#define NHEAD 204
#define NHEAD_PAD 256
#define CAP   2048
#define EPS_F 2.220446049250313e-16f

// shared tiling params
#define BM 128
#define BK 32
#define KPW 16
#define A_STRIDE 20
#define A_STAGE (BM * A_STRIDE * 4)
#define NSTAGE 6

// main GEMM: BN=256, 512 threads
#define BNW 256
#define BW_STRIDE 264
#define BW_STAGE (16 * BW_STRIDE * 4)
#define STAGE_W (A_STAGE + BW_STAGE)
#define SMEM_MAIN (NSTAGE * STAGE_W)       // 162816

// heads GEMM: BN=128, 256 threads
#define BNH 128
#define BH_STRIDE 136
#define BH_STAGE (16 * BH_STRIDE * 4)
#define STAGE_H (A_STAGE + BH_STAGE)
#define SMEM_HEADS (NSTAGE * STAGE_H)      // 113664

// prep kernel block ranges
#define G_BLKS  2048
#define W1_BLKS 12288
#define W2_BLKS 8192
#define PH_BLKS 8192
#define PREP_BLKS (G_BLKS + W1_BLKS + W2_BLKS + PH_BLKS)

// ---------------- scratch ----------------
__device__ __align__(16) uint32_t g_xb[(size_t)B_TOK * (D_IN / 2)];   // single bf16 copy of x
__device__ int   g_rows[E_EXP * CAP];                                  // slot -> token
__device__ int   g_cnt[E_EXP];
__device__ float g_gate[B_TOK * TOPK];
__device__ int   g_slot[B_TOK * TOPK];
__device__ __align__(16) uint32_t g_h1[(size_t)E_EXP * CAP * (H_DIM / 2)];
__device__ __align__(16) uint32_t g_h2[(size_t)E_EXP * CAP * (H_DIM / 2)];
__device__ __align__(16) float    g_hl[(size_t)E_EXP * CAP * NHEAD_PAD];
__device__ __align__(16) float    g_hl2[(size_t)E_EXP * CAP * NHEAD_PAD];
__device__ __align__(16) uint32_t g_w1b[(size_t)E_EXP * (D_IN / 2) * H_DIM];
__device__ __align__(16) uint32_t g_w2b[(size_t)E_EXP * (H_DIM / 2) * H_DIM];
__device__ __align__(16) uint32_t g_whb[(size_t)E_EXP * (H_DIM / 2) * NHEAD_PAD];
__device__ float g_bh[E_EXP * NHEAD_PAD];

// ---------------- helpers ----------------
__device__ __forceinline__ uint32_t smem_u32(const void* p) {
    uint32_t a;
    asm("{ .reg .u64 t; cvta.to.shared.u64 t, %1; cvt.u32.u64 %0, t; }" : "=r"(a) : "l"(p));
    return a;
}
__device__ __forceinline__ uint32_t packbf(float lo, float hi) {
    uint32_t w;
    asm("cvt.rn.bf16x2.f32 %0, %1, %2;" : "=r"(w) : "f"(hi), "f"(lo));
    return w;
}
__device__ __forceinline__ void cp16(uint32_t dst, const void* src) {
    asm volatile("cp.async.cg.shared.global [%0], [%1], 16;" :: "r"(dst), "l"(src));
}
__device__ __forceinline__ void mma_bf16(float* c, const uint32_t* a, const uint32_t* b) {
    asm volatile("mma.sync.aligned.m16n8k16.row.col.f32.bf16.bf16.f32 "
        "{%0,%1,%2,%3}, {%4,%5,%6,%7}, {%8,%9}, {%0,%1,%2,%3};"
        : "+f"(c[0]), "+f"(c[1]), "+f"(c[2]), "+f"(c[3])
        : "r"(a[0]), "r"(a[1]), "r"(a[2]), "r"(a[3]), "r"(b[0]), "r"(b[1]));
}
__device__ __forceinline__ void ldm_x4(uint32_t* r, uint32_t addr) {
    asm volatile("ldmatrix.sync.aligned.m8n8.x4.shared.b16 {%0,%1,%2,%3}, [%4];"
        : "=r"(r[0]), "=r"(r[1]), "=r"(r[2]), "=r"(r[3]) : "r"(addr));
}

// ---------------- conv body ----------------
__device__ __forceinline__ void conv_body(const float* __restrict__ src,
                                          uint32_t* __restrict__ dst,
                                          int Khalf, int N, int bb) {
    size_t idx = ((size_t)bb * 256 + threadIdx.x) * 4;
    size_t n   = idx % N;
    size_t kpe = idx / N;
    size_t kp  = kpe % Khalf;
    size_t e   = kpe / Khalf;
    const float* s = src + ((size_t)e * (2 * Khalf) + 2 * kp) * N + n;
    float4 lo = *(const float4*)s;
    float4 hi = *(const float4*)(s + N);
    uint4 o;
    o.x = packbf(lo.x, hi.x);
    o.y = packbf(lo.y, hi.y);
    o.z = packbf(lo.z, hi.z);
    o.w = packbf(lo.w, hi.w);
    *(uint4*)(dst + idx) = o;
}

// ---------------- fused prep: gating + W1 conv + W2 conv + head pack ----------------
__global__ void __launch_bounds__(256)
prep_kernel(const float* __restrict__ sf, const float* __restrict__ of,
            const float* __restrict__ ppf, const float* __restrict__ pvf,
            const float* __restrict__ wg, const float* __restrict__ wn,
            const float* __restrict__ noise,
            const float* __restrict__ W1, const float* __restrict__ W2,
            const float* __restrict__ Ws, const float* __restrict__ bs,
            const float* __restrict__ Wo, const float* __restrict__ bo,
            const float* __restrict__ Wp, const float* __restrict__ bp) {
    int bb = blockIdx.x;
    int t = threadIdx.x;

    if (bb >= G_BLKS) {
        bb -= G_BLKS;
        if (bb < W1_BLKS) { conv_body(W1, g_w1b, D_IN / 2, H_DIM, bb); return; }
        bb -= W1_BLKS;
        if (bb < W2_BLKS) { conv_body(W2, g_w2b, H_DIM / 2, H_DIM, bb); return; }
        bb -= W2_BLKS;
        size_t idx = (size_t)bb * 256 + t;
        int n  = (int)(idx & 255);
        int kp = (int)((idx >> 8) & 511);
        int e  = (int)(idx >> 17);
        float lo = 0.f, hi = 0.f;
        size_t base0 = (size_t)e * H_DIM + 2 * kp;
        if (n < 36)       { lo = Ws[base0 * 36 + n];         hi = Ws[(base0 + 1) * 36 + n]; }
        else if (n < 72)  { lo = Wo[base0 * 36 + (n - 36)];  hi = Wo[(base0 + 1) * 36 + (n - 36)]; }
        else if (n < 204) { lo = Wp[base0 * 132 + (n - 72)]; hi = Wp[(base0 + 1) * 132 + (n - 72)]; }
        g_whb[idx] = packbf(lo, hi);
        if (idx < E_EXP * NHEAD_PAD) {
            int nn = (int)(idx & 255), ee = (int)(idx >> 8);
            float b = 0.0f;
            if (nn < 36)       b = bs[ee * 36 + nn];
            else if (nn < 72)  b = bo[ee * 36 + (nn - 36)];
            else if (nn < 204) b = bp[ee * 132 + (nn - 72)];
            g_bh[idx] = b;
        }
        return;
    }

    // ----- gating block -----
    int b = bb;
    __shared__ __align__(16) float sx[D_IN];
    __shared__ float part[8][32];

    for (int i = t; i < D_IN; i += 256) {
        float v;
        if (i < 512)        v = sf[b * 512 + i];
        else if (i < 1024)  v = of[b * 512 + (i - 512)];
        else if (i < 1280)  v = ppf[b * 256 + (i - 1024)];
        else                v = pvf[b * 256 + (i - 1280)];
        sx[i] = v;
    }
    __syncthreads();

    int w = t >> 5, lane = t & 31;
    int e = lane & 15;
    const float* wm = (lane < 16) ? wg : wn;
    int d0 = w * 192;
    float a0 = 0.f, a1 = 0.f, a2 = 0.f, a3 = 0.f;
    #pragma unroll 4
    for (int d = d0; d < d0 + 192; d += 4) {
        a0 += sx[d + 0] * wm[(d + 0) * 16 + e];
        a1 += sx[d + 1] * wm[(d + 1) * 16 + e];
        a2 += sx[d + 2] * wm[(d + 2) * 16 + e];
        a3 += sx[d + 3] * wm[(d + 3) * 16 + e];
    }
    part[w][lane] = (a0 + a1) + (a2 + a3);
    __syncthreads();

    if (t < 32) {
        float s = 0.f;
        #pragma unroll
        for (int w2 = 0; w2 < 8; w2++) s += part[w2][t];
        part[0][t] = s;
    }
    __syncthreads();

    if (t == 0) {
        float logits[16];
        #pragma unroll
        for (int i = 0; i < 16; i++) {
            float cl = part[0][i];
            float z  = part[0][16 + i];
            float sp = (z > 20.f) ? z : log1pf(expf(z));
            logits[i] = cl + noise[b * 16 + i] * (sp + 1e-2f);
        }
        int   idx[TOPK];
        float val[TOPK];
        unsigned used = 0u;
        for (int k = 0; k < TOPK; k++) {
            float best = -INFINITY; int bi = 0;
            for (int i = 0; i < 16; i++)
                if (!((used >> i) & 1u) && logits[i] > best) { best = logits[i]; bi = i; }
            used |= (1u << bi); idx[k] = bi; val[k] = best;
        }
        float m = val[0];
        float g[TOPK], s = 0.f;
        #pragma unroll
        for (int k = 0; k < TOPK; k++) { g[k] = expf(val[k] - m); s += g[k]; }
        #pragma unroll
        for (int k = 0; k < TOPK; k++) {
            int ex = idx[k];
            int rank = atomicAdd(&g_cnt[ex], 1);
            int slot = ex * CAP + rank;
            g_rows[slot]       = b;
            g_slot[b * 4 + k]  = slot;
            g_gate[b * 4 + k]  = g[k] / s;
        }
    }

    // single packed bf16 copy of x
    uint32_t* dst = g_xb + (size_t)b * (D_IN / 2);
    for (int i = t; i < D_IN / 2; i += 256)
        dst[i] = packbf(sx[2 * i], sx[2 * i + 1]);
}

// ---------------- main bf16 GEMM: 128x256 tile, 512 threads, optional row gather ----------------
template<bool GATHER>
__global__ void __launch_bounds__(512, 1)
gemm_main(const uint32_t* __restrict__ A, const uint32_t* __restrict__ B,
          const float* __restrict__ bias, uint32_t* __restrict__ C,
          int Ktot, int Ntot) {
    extern __shared__ char smem[];
    const int e  = blockIdx.z;
    const int M  = g_cnt[e];
    const int m0 = blockIdx.y * BM;
    if (m0 >= M) return;
    const int n0 = blockIdx.x * BNW;

    const uint32_t sbase = smem_u32(smem);
    const int tid = threadIdx.x;
    const int wid = tid >> 5, lane = tid & 31;
    const int wm = wid >> 3;
    const int wn = wid & 7;
    const int r  = lane >> 2;
    const int c  = lane & 3;

    const int Kw = Ktot / 2;
    const uint32_t* Bbase = B + (size_t)e * Kw * Ntot + n0;
    const int KT = Ktot / BK;

    const int a_row = tid >> 2;              // 0..127 (fixed row per thread)
    const int a_ch  = tid & 3;
    const int b_row = tid >> 5;
    const int b_ch  = (tid & 31) * 2;

    // per-thread A source row pointer (gather resolved once)
    const uint32_t* ga_row;
    if (GATHER) {
        int mg = m0 + a_row;
        if (mg >= M) mg = M - 1;
        ga_row = A + (size_t)g_rows[e * CAP + mg] * Kw;
    } else {
        ga_row = A + (size_t)(e * CAP + m0 + a_row) * Kw;
    }

    auto load_stage = [&](int kt) {
        int slot = kt % NSTAGE;
        uint32_t sa = sbase + slot * STAGE_W;
        uint32_t sb = sa + A_STAGE;
        const uint32_t* gb = Bbase + (size_t)(kt * 16) * Ntot;
        cp16(sa + a_row * (A_STRIDE * 4) + a_ch * 16, ga_row + kt * KPW + a_ch * 4);
        cp16(sb + b_row * (BW_STRIDE * 4) + b_ch * 16,       gb + (size_t)b_row * Ntot + b_ch * 4);
        cp16(sb + b_row * (BW_STRIDE * 4) + (b_ch + 1) * 16, gb + (size_t)b_row * Ntot + (b_ch + 1) * 4);
        asm volatile("cp.async.commit_group;" ::: "memory");
    };

    load_stage(0);
    load_stage(1);
    load_stage(2);
    load_stage(3);

    float acc[4][4][4];
    #pragma unroll
    for (int i = 0; i < 4; i++)
        #pragma unroll
        for (int j = 0; j < 4; j++)
            #pragma unroll
            for (int k = 0; k < 4; k++) acc[i][j][k] = 0.f;

    const int lrow = lane & 7;
    const int lsel = lane >> 3;
    const uint32_t a_lm = sbase
        + ((wm * 64 + (lsel & 1) * 8 + lrow) * A_STRIDE) * 4
        + (lsel >> 1) * 16;
    const uint32_t b_fb = sbase + A_STAGE + (c * BW_STRIDE + wn * 32 + r) * 4;

    auto process = [&](int s) {
        int slot = s % NSTAGE;
        uint32_t sa = a_lm + slot * STAGE_W;
        uint32_t sb = b_fb + slot * STAGE_W;
        #pragma unroll
        for (int ks = 0; ks < 2; ks++) {
            uint32_t af[4][4];
            #pragma unroll
            for (int mt = 0; mt < 4; mt++)
                ldm_x4(af[mt], sa + mt * (16 * A_STRIDE * 4) + ks * 32);
            uint32_t bf[4][2];
            #pragma unroll
            for (int nt = 0; nt < 4; nt++) {
                uint32_t base = sb + ks * (8 * BW_STRIDE * 4) + nt * 32;
                asm volatile("ld.shared.b32 %0, [%1];" : "=r"(bf[nt][0]) : "r"(base));
                asm volatile("ld.shared.b32 %0, [%1];" : "=r"(bf[nt][1]) : "r"(base + 4 * BW_STRIDE * 4));
            }
            #pragma unroll
            for (int mt = 0; mt < 4; mt++)
                #pragma unroll
                for (int nt = 0; nt < 4; nt++)
                    mma_bf16(acc[mt][nt], af[mt], bf[nt]);
        }
    };

    for (int kt = 0; kt < KT; kt += 2) {
        asm volatile("cp.async.wait_group 2;" ::: "memory");
        __syncthreads();
        if (kt + 4 < KT) load_stage(kt + 4);
        else asm volatile("cp.async.commit_group;" ::: "memory");
        if (kt + 5 < KT) load_stage(kt + 5);
        else asm volatile("cp.async.commit_group;" ::: "memory");
        process(kt);
        process(kt + 1);
    }
    asm volatile("cp.async.wait_group 0;" ::: "memory");

    #pragma unroll
    for (int nt = 0; nt < 4; nt++) {
        int col = n0 + wn * 32 + nt * 8 + 2 * c;
        float bb0 = __ldg(bias + e * Ntot + col);
        float bb1 = __ldg(bias + e * Ntot + col + 1);
        #pragma unroll
        for (int mt = 0; mt < 4; mt++) {
            int row0 = wm * 64 + mt * 16 + r;
            float v0 = fmaxf(acc[mt][nt][0] + bb0, 0.f);
            float v1 = fmaxf(acc[mt][nt][1] + bb1, 0.f);
            float v2 = fmaxf(acc[mt][nt][2] + bb0, 0.f);
            float v3 = fmaxf(acc[mt][nt][3] + bb1, 0.f);
            int cw = col >> 1;
            if (m0 + row0 < M)
                C[(size_t)(e * CAP + m0 + row0) * (Ntot / 2) + cw] = packbf(v0, v1);
            if (m0 + row0 + 8 < M)
                C[(size_t)(e * CAP + m0 + row0 + 8) * (Ntot / 2) + cw] = packbf(v2, v3);
        }
    }
}

// ---------------- heads GEMM, split-K=2, BN=128 ----------------
__global__ void __launch_bounds__(256, 2)
gemm_heads(const uint32_t* __restrict__ A, const uint32_t* __restrict__ B) {
    extern __shared__ char smem[];
    const int zz = blockIdx.z;
    const int e  = zz & 15;
    const int sp = zz >> 4;
    const int M  = g_cnt[e];
    const int m0 = blockIdx.y * BM;
    if (m0 >= M) return;
    const int n0 = blockIdx.x * BNH;

    const uint32_t sbase = smem_u32(smem);
    const int tid = threadIdx.x;
    const int wid = tid >> 5, lane = tid & 31;
    const int wm = wid >> 2;
    const int wn = wid & 3;
    const int r  = lane >> 2;
    const int c  = lane & 3;

    const int Kw = H_DIM / 2;
    const int KT = (H_DIM / 2) / BK;
    const uint32_t* Abase = A + (size_t)(e * CAP + m0) * Kw + sp * (Kw / 2);
    const uint32_t* Bbase = B + ((size_t)e * Kw + sp * (Kw / 2)) * NHEAD_PAD + n0;
    float* C = (sp ? g_hl2 : g_hl);

    const int a_row = tid >> 1;
    const int a_ch  = (tid & 1) * 2;
    const int b_row = tid >> 4;
    const int b_ch  = (tid & 15) * 2;

    auto load_stage = [&](int kt) {
        int slot = kt % NSTAGE;
        uint32_t sa = sbase + slot * STAGE_H;
        uint32_t sb = sa + A_STAGE;
        const uint32_t* ga = Abase + kt * KPW;
        const uint32_t* gb = Bbase + (size_t)(kt * 16) * NHEAD_PAD;
        cp16(sa + a_row * (A_STRIDE * 4) + a_ch * 16,       ga + (size_t)a_row * Kw + a_ch * 4);
        cp16(sa + a_row * (A_STRIDE * 4) + (a_ch + 1) * 16, ga + (size_t)a_row * Kw + (a_ch + 1) * 4);
        cp16(sb + b_row * (BH_STRIDE * 4) + b_ch * 16,       gb + (size_t)b_row * NHEAD_PAD + b_ch * 4);
        cp16(sb + b_row * (BH_STRIDE * 4) + (b_ch + 1) * 16, gb + (size_t)b_row * NHEAD_PAD + (b_ch + 1) * 4);
        asm volatile("cp.async.commit_group;" ::: "memory");
    };

    load_stage(0);
    load_stage(1);
    load_stage(2);
    load_stage(3);

    float acc[4][4][4];
    #pragma unroll
    for (int i = 0; i < 4; i++)
        #pragma unroll
        for (int j = 0; j < 4; j++)
            #pragma unroll
            for (int k = 0; k < 4; k++) acc[i][j][k] = 0.f;

    const int lrow = lane & 7;
    const int lsel = lane >> 3;
    const uint32_t a_lm = sbase
        + ((wm * 64 + (lsel & 1) * 8 + lrow) * A_STRIDE) * 4
        + (lsel >> 1) * 16;
    const uint32_t b_fb = sbase + A_STAGE + (c * BH_STRIDE + wn * 32 + r) * 4;

    auto process = [&](int s) {
        int slot = s % NSTAGE;
        uint32_t sa = a_lm + slot * STAGE_H;
        uint32_t sb = b_fb + slot * STAGE_H;
        #pragma unroll
        for (int ks = 0; ks < 2; ks++) {
            uint32_t af[4][4];
            #pragma unroll
            for (int mt = 0; mt < 4; mt++)
                ldm_x4(af[mt], sa + mt * (16 * A_STRIDE * 4) + ks * 32);
            uint32_t bf[4][2];
            #pragma unroll
            for (int nt = 0; nt < 4; nt++) {
                uint32_t base = sb + ks * (8 * BH_STRIDE * 4) + nt * 32;
                asm volatile("ld.shared.b32 %0, [%1];" : "=r"(bf[nt][0]) : "r"(base));
                asm volatile("ld.shared.b32 %0, [%1];" : "=r"(bf[nt][1]) : "r"(base + 4 * BH_STRIDE * 4));
            }
            #pragma unroll
            for (int mt = 0; mt < 4; mt++)
                #pragma unroll
                for (int nt = 0; nt < 4; nt++)
                    mma_bf16(acc[mt][nt], af[mt], bf[nt]);
        }
    };

    for (int kt = 0; kt < KT; kt += 2) {
        asm volatile("cp.async.wait_group 2;" ::: "memory");
        __syncthreads();
        if (kt + 4 < KT) load_stage(kt + 4);
        else asm volatile("cp.async.commit_group;" ::: "memory");
        if (kt + 5 < KT) load_stage(kt + 5);
        else asm volatile("cp.async.commit_group;" ::: "memory");
        process(kt);
        process(kt + 1);
    }
    asm volatile("cp.async.wait_group 0;" ::: "memory");

    #pragma unroll
    for (int nt = 0; nt < 4; nt++) {
        int col = n0 + wn * 32 + nt * 8 + 2 * c;
        #pragma unroll
        for (int mt = 0; mt < 4; mt++) {
            int row0 = wm * 64 + mt * 16 + r;
            if (m0 + row0 < M) {
                float2 p = {acc[mt][nt][0], acc[mt][nt][1]};
                *(float2*)(C + (size_t)(e * CAP + m0 + row0) * NHEAD_PAD + col) = p;
            }
            if (m0 + row0 + 8 < M) {
                float2 p = {acc[mt][nt][2], acc[mt][nt][3]};
                *(float2*)(C + (size_t)(e * CAP + m0 + row0 + 8) * NHEAD_PAD + col) = p;
            }
        }
    }
}

// ---------------- combine ----------------
__global__ void combine_kernel(float* __restrict__ out) {
    int b = blockIdx.x;
    __shared__ float vals[TOPK][NHEAD];
    __shared__ float mx[TOPK][3], inv[TOPK][3];
    __shared__ int   slots[TOPK];
    __shared__ float gts[TOPK];
    int t = threadIdx.x;

    if (b == 0 && t >= 32 && t < 32 + E_EXP) g_cnt[t - 32] = 0;

    if (t < TOPK) { slots[t] = g_slot[b * 4 + t]; gts[t] = g_gate[b * 4 + t]; }
    __syncthreads();

    for (int i = t; i < TOPK * NHEAD; i += 256) {
        int k = i / NHEAD, cc = i % NHEAD;
        int slot = slots[k];
        int e = slot >> 11;
        vals[k][cc] = g_hl[(size_t)slot * NHEAD_PAD + cc]
                    + g_hl2[(size_t)slot * NHEAD_PAD + cc]
                    + g_bh[e * NHEAD_PAD + cc];
    }
    __syncthreads();

    if (t < TOPK * 3) {
        int k = t / 3, grp = t % 3;
        int c0 = (grp == 0) ? 0 : (grp == 1 ? 36 : 72);
        int c1 = (grp == 0) ? 36 : (grp == 1 ? 72 : 204);
        float m = -INFINITY;
        for (int cc = c0; cc < c1; cc++) m = fmaxf(m, vals[k][cc]);
        float s = 0.f;
        for (int cc = c0; cc < c1; cc++) s += expf(vals[k][cc] - m);
        mx[k][grp]  = m;
        inv[k][grp] = 1.f / s;
    }
    __syncthreads();

    if (t < NHEAD) {
        int grp = (t < 36) ? 0 : ((t < 72) ? 1 : 2);
        float s = 0.f;
        #pragma unroll
        for (int k = 0; k < TOPK; k++)
            s += gts[k] * expf(vals[k][t] - mx[k][grp]) * inv[k][grp];
        float res = logf((s == 0.f) ? EPS_F : s);
        if (t < 36)       out[b * 36 + t] = res;
        else if (t < 72)  out[B_TOK * 36 + b * 36 + (t - 36)] = res;
        else              out[B_TOK * 72 + b * 132 + (t - 72)] = res;
    }
}

// ---------------- launch ----------------
extern "C" void kernel_launch(void* const* d_in, const int* in_sizes, int n_in,
                              void* d_out, int out_size) {
    const float* sf  = (const float*)d_in[0];
    const float* of  = (const float*)d_in[1];
    const float* ppf = (const float*)d_in[2];
    const float* pvf = (const float*)d_in[3];
    const float* wg  = (const float*)d_in[4];
    const float* wn  = (const float*)d_in[5];
    const float* W1  = (const float*)d_in[6];
    const float* b1  = (const float*)d_in[7];
    const float* W2  = (const float*)d_in[8];
    const float* b2  = (const float*)d_in[9];
    const float* Ws  = (const float*)d_in[10];
    const float* bs  = (const float*)d_in[11];
    const float* Wo  = (const float*)d_in[12];
    const float* bo  = (const float*)d_in[13];
    const float* Wp  = (const float*)d_in[14];
    const float* bp  = (const float*)d_in[15];
    const float* noise = (const float*)d_in[16];
    float* out = (float*)d_out;

    static uint32_t* p_xb  = nullptr;
    static uint32_t* p_h1  = nullptr;
    static uint32_t* p_h2  = nullptr;
    static uint32_t* p_w1b = nullptr;
    static uint32_t* p_w2b = nullptr;
    static uint32_t* p_whb = nullptr;
    if (!p_xb) {
        cudaGetSymbolAddress((void**)&p_xb,  g_xb);
        cudaGetSymbolAddress((void**)&p_h1,  g_h1);
        cudaGetSymbolAddress((void**)&p_h2,  g_h2);
        cudaGetSymbolAddress((void**)&p_w1b, g_w1b);
        cudaGetSymbolAddress((void**)&p_w2b, g_w2b);
        cudaGetSymbolAddress((void**)&p_whb, g_whb);
        cudaFuncSetAttribute(gemm_main<true>,
                             cudaFuncAttributeMaxDynamicSharedMemorySize, SMEM_MAIN);
        cudaFuncSetAttribute(gemm_main<false>,
                             cudaFuncAttributeMaxDynamicSharedMemorySize, SMEM_MAIN);
        cudaFuncSetAttribute(gemm_heads,
                             cudaFuncAttributeMaxDynamicSharedMemorySize, SMEM_HEADS);
    }

    prep_kernel<<<PREP_BLKS, 256>>>(sf, of, ppf, pvf, wg, wn, noise,
                                    W1, W2, Ws, bs, Wo, bo, Wp, bp);

    // L1: gathered rows of x (single bf16 copy) @ W1[e] -> relu -> h1
    gemm_main<true><<<dim3(H_DIM / BNW, CAP / BM, E_EXP), 512, SMEM_MAIN>>>(
        p_xb, p_w1b, b1, p_h1, D_IN, H_DIM);
    // L2: slot-major h1 @ W2[e] -> relu -> h2
    gemm_main<false><<<dim3(H_DIM / BNW, CAP / BM, E_EXP), 512, SMEM_MAIN>>>(
        p_h1, p_w2b, b2, p_h2, H_DIM, H_DIM);
    // heads: split-K=2
    gemm_heads<<<dim3(NHEAD_PAD / BNH, CAP / BM, 2 * E_EXP), 256, SMEM_HEADS>>>(p_h2, p_whb);

    combine_kernel<<<B_TOK, 256>>>(out);
}